// round 6
// baseline (speedup 1.0000x reference)
#include <cuda_runtime.h>
#include <math.h>

#define NN 50000
#define EE 512000
#define BG 64

// ---------------- scratch ----------------
__device__ float g_h[NN * 64];
__device__ float g_q[NN * 256];         // q'(scaled)[0:128) skip[128:192) u[192:208) qb[208:210)
__device__ float g_kv[NN * 256];        // k[0:128) v[128:256)
__device__ float g_outp[NN * 64];
__device__ float g_Wall[2 * 64 * 512];
__device__ float g_ball[2 * 512];
__device__ float g_Wf[2 * 1024];        // edge_W @ We[i]  [8,128]
__device__ float g_bf[2 * 128];
__device__ float g_stats[128];          // zeroed after each use (invariant across calls)
__device__ float g_bn[128];
__device__ float g_pool[BG * 64];
__device__ float g_gden[BG];
// CSR (g_deg/g_cur: zero-initialized at load; re-zeroed at end of each call in pool)
__device__ int g_deg[NN];
__device__ int g_cur[NN];
__device__ int g_off[NN + 1];
__device__ int g_bsum[256];
__device__ int g_boff[256];
__device__ int g_srcs[EE];
__device__ float g_eatp[EE * 8];        // edge_attr permuted into CSR order

typedef unsigned long long ull;

// ---------------- f32x2 helpers ----------------
__device__ __forceinline__ ull pack2(float x, float y) {
    ull d;
    asm("mov.b64 %0, {%1, %2};" : "=l"(d) : "r"(__float_as_uint(x)), "r"(__float_as_uint(y)));
    return d;
}
__device__ __forceinline__ ull ffma2(ull a, ull b, ull c) {
    ull d;
    asm("fma.rn.f32x2 %0, %1, %2, %3;" : "=l"(d) : "l"(a), "l"(b), "l"(c));
    return d;
}
__device__ __forceinline__ ull add2(ull a, ull b) {
    ull d;
    asm("add.rn.f32x2 %0, %1, %2;" : "=l"(d) : "l"(a), "l"(b));
    return d;
}
__device__ __forceinline__ float2 unpack2(ull v) {
    unsigned int lo, hi;
    asm("mov.b64 {%0, %1}, %2;" : "=r"(lo), "=r"(hi) : "l"(v));
    return make_float2(__uint_as_float(lo), __uint_as_float(hi));
}

// ---------------- setup1: base fused weights (q scaled by 1/8) ----------------
__global__ void setup1_kernel(const float* __restrict__ Wq, const float* __restrict__ bq,
                              const float* __restrict__ Wk, const float* __restrict__ bk,
                              const float* __restrict__ Wv, const float* __restrict__ bv,
                              const float* __restrict__ Wskip, const float* __restrict__ bskip,
                              const float* __restrict__ edge_W, const float* __restrict__ edge_b,
                              const float* __restrict__ We, const float* __restrict__ be) {
    const int TOT = 65536 + 1024 + 2048 + 256;
    for (int idx = blockIdx.x * blockDim.x + threadIdx.x; idx < TOT;
         idx += gridDim.x * blockDim.x) {
        if (idx < 65536) {
            int c = idx & 511, j = (idx >> 9) & 63, i = idx >> 15;
            float v = 0.f;
            if (c < 128)      v = 0.125f * Wq[(i * 64 + j) * 128 + c];
            else if (c < 256) v = Wk[(i * 64 + j) * 128 + (c - 128)];
            else if (c < 384) v = Wv[(i * 64 + j) * 128 + (c - 256)];
            else if (c < 448) v = Wskip[(i * 64 + j) * 64 + (c - 384)];
            g_Wall[idx] = v;
        } else if (idx < 66560) {
            int t = idx - 65536; int c = t & 511, i = t >> 9;
            float v = 0.f;
            if (c < 128)      v = 0.125f * bq[i * 128 + c];
            else if (c < 256) v = bk[i * 128 + (c - 128)];
            else if (c < 384) v = bv[i * 128 + (c - 256)];
            else if (c < 448) v = bskip[i * 64 + (c - 384)];
            g_ball[t] = v;
        } else if (idx < 68608) {
            int t = idx - 66560; int i = t >> 10; int r = t & 1023;
            int j = r >> 7; int c = r & 127;
            float acc = 0.f;
            #pragma unroll 8
            for (int m = 0; m < 64; m++) acc += edge_W[j * 64 + m] * We[(i * 64 + m) * 128 + c];
            g_Wf[t] = acc;
        } else {
            int t = idx - 68608; int i = t >> 7; int c = t & 127;
            float acc = be[i * 128 + c];
            #pragma unroll 8
            for (int m = 0; m < 64; m++) acc += edge_b[m] * We[(i * 64 + m) * 128 + c];
            g_bf[i * 128 + c] = acc;
        }
    }
}

// ---------------- setup2: u / qb columns ----------------
__global__ void setup2_kernel() {
    int idx = blockIdx.x * blockDim.x + threadIdx.x;
    if (idx < 2 * 64 * 18) {
        int i = idx / (64 * 18); int r = idx % (64 * 18);
        int m = r / 18; int col = r % 18;
        const float* Wf = g_Wf + i * 1024;
        const float* bf = g_bf + i * 128;
        const float* Wrow = g_Wall + i * 64 * 512 + m * 512;
        float acc = 0.f;
        if (col < 16) {
            int h = col >> 3, j = col & 7;
            #pragma unroll 8
            for (int c = 0; c < 64; c++) acc += Wrow[h * 64 + c] * Wf[j * 128 + h * 64 + c];
            g_Wall[i * 64 * 512 + m * 512 + 448 + col] = acc;
        } else {
            int h = col - 16;
            #pragma unroll 8
            for (int c = 0; c < 64; c++) acc += Wrow[h * 64 + c] * bf[h * 64 + c];
            g_Wall[i * 64 * 512 + m * 512 + 464 + h] = acc;
        }
    } else if (idx < 2 * 64 * 18 + 2 * 18) {
        int t = idx - 2 * 64 * 18; int i = t / 18; int col = t % 18;
        const float* Wf = g_Wf + i * 1024;
        const float* bf = g_bf + i * 128;
        const float* Brow = g_ball + i * 512;
        float acc = 0.f;
        if (col < 16) {
            int h = col >> 3, j = col & 7;
            #pragma unroll 8
            for (int c = 0; c < 64; c++) acc += Brow[h * 64 + c] * Wf[j * 128 + h * 64 + c];
            g_ball[i * 512 + 448 + col] = acc;
        } else {
            int h = col - 16;
            #pragma unroll 8
            for (int c = 0; c < 64; c++) acc += Brow[h * 64 + c] * bf[h * 64 + c];
            g_ball[i * 512 + 464 + h] = acc;
        }
    }
}

// ---------------- node encoder ----------------
__global__ void __launch_bounds__(256) node_enc_kernel(const float* __restrict__ x,
                                                       const float* __restrict__ W,
                                                       const float* __restrict__ b, int n) {
    __shared__ float Ws[16 * 64];
    __shared__ float bs[64];
    int tid = threadIdx.x;
    for (int i = tid; i < 1024; i += 256) Ws[i] = W[i];
    if (tid < 64) bs[tid] = b[tid];
    __syncthreads();
    int idx = blockIdx.x * 256 + tid;
    if (idx >= n * 64) return;
    int nn = idx >> 6, c = idx & 63;
    const float* xr = x + nn * 16;
    float acc = bs[c];
    #pragma unroll
    for (int j = 0; j < 16; j++) acc += xr[j] * Ws[j * 64 + c];
    g_h[idx] = acc;
}

// ---------------- CSR build ----------------
__global__ void csr_hist_kernel(const int* __restrict__ edst, int E) {
    int e = blockIdx.x * blockDim.x + threadIdx.x;
    if (e < E) atomicAdd(&g_deg[edst[e]], 1);
}
__global__ void scan1_kernel(int n) {
    __shared__ int sd[256];
    int i = blockIdx.x * 256 + threadIdx.x;
    int v = (i < n) ? g_deg[i] : 0;
    sd[threadIdx.x] = v;
    __syncthreads();
    for (int off = 128; off > 0; off >>= 1) {
        if (threadIdx.x < off) sd[threadIdx.x] += sd[threadIdx.x + off];
        __syncthreads();
    }
    if (threadIdx.x == 0) g_bsum[blockIdx.x] = sd[0];
}
__global__ void scan2_kernel(int nb, int n, int E) {
    __shared__ int sd[256];
    int tid = threadIdx.x;
    int v = (tid < nb) ? g_bsum[tid] : 0;
    sd[tid] = v;
    __syncthreads();
    for (int off = 1; off < 256; off <<= 1) {
        int t = (tid >= off) ? sd[tid - off] : 0;
        __syncthreads();
        sd[tid] += t;
        __syncthreads();
    }
    if (tid < nb) g_boff[tid] = sd[tid] - v;
    if (tid == 0) g_off[n] = E;
}
__global__ void scan3_kernel(int n) {
    __shared__ int sd[256];
    int tid = threadIdx.x;
    int i = blockIdx.x * 256 + tid;
    int v = (i < n) ? g_deg[i] : 0;
    sd[tid] = v;
    __syncthreads();
    for (int off = 1; off < 256; off <<= 1) {
        int t = (tid >= off) ? sd[tid - off] : 0;
        __syncthreads();
        sd[tid] += t;
        __syncthreads();
    }
    if (i < n) g_off[i] = g_boff[blockIdx.x] + sd[tid] - v;
}
__global__ void csr_scatter_kernel(const float* __restrict__ eat,
                                   const int* __restrict__ esrc, const int* __restrict__ edst,
                                   int E) {
    int e = blockIdx.x * blockDim.x + threadIdx.x;
    if (e >= E) return;
    int d = edst[e];
    int pos = atomicAdd(&g_cur[d], 1);
    int slot = g_off[d] + pos;
    g_srcs[slot] = esrc[e];
    float4 a0 = *(const float4*)(eat + (size_t)e * 8);
    float4 a1 = *(const float4*)(eat + (size_t)e * 8 + 4);
    *(float4*)(g_eatp + (size_t)slot * 8) = a0;
    *(float4*)(g_eatp + (size_t)slot * 8 + 4) = a1;
}

// ---------------- fused q'/k/v/skip/u/qb GEMM (f32x2, pre-duplicated weights) ----------------
__global__ void __launch_bounds__(256, 4) qkvs_kernel(int layer, int n, int fuse,
                                                      const float* __restrict__ gamma,
                                                      const float* __restrict__ beta) {
    __shared__ float hs_t[64 * 66];     // [j][r] transposed h tile
    __shared__ ull Wsd[32 * 128];       // half-panel weights, duplicated f32x2 (32 KB)
    const float* Wall = g_Wall + layer * 64 * 512;
    const float* ball = g_ball + layer * 512;
    int tid = threadIdx.x;
    int n0 = blockIdx.x * 64;

    for (int i = tid; i < 4096; i += 256) {
        int r = i >> 6, j = i & 63;
        int nn = n0 + r;
        float v = 0.f;
        if (nn < n) {
            if (fuse) {
                float o = g_outp[nn * 64 + j];
                float hv = g_h[nn * 64 + j];
                float bnv = __ldg(&gamma[j]) * (o - g_bn[j]) * g_bn[64 + j] + __ldg(&beta[j]);
                bnv = (bnv > 0.f) ? bnv : 0.01f * bnv;
                v = hv + bnv;
                g_h[nn * 64 + j] = v;
            } else {
                v = g_h[nn * 64 + j];
            }
        }
        hs_t[j * 66 + r] = v;
    }

    int ng = tid >> 5;          // warp-uniform row group (8 rows)
    int cg = (tid & 31) * 4;    // 4 cols within panel

    for (int p4 = 0; p4 < 4; p4++) {
        ull acc[4][4];
        #pragma unroll
        for (int a = 0; a < 4; a++)
            #pragma unroll
            for (int b = 0; b < 4; b++) acc[a][b] = 0ull;

        for (int half = 0; half < 2; half++) {
            __syncthreads();
            for (int i = tid; i < 4096; i += 256) {
                float w = Wall[(half * 32 + (i >> 7)) * 512 + p4 * 128 + (i & 127)];
                Wsd[i] = pack2(w, w);
            }
            __syncthreads();

            const float* hbase = &hs_t[half * 32 * 66 + ng * 8];
            #pragma unroll 4
            for (int j = 0; j < 32; j++) {
                const float* hrow = hbase + j * 66;
                ull h0 = *(const ull*)(hrow + 0);
                ull h1 = *(const ull*)(hrow + 2);
                ull h2 = *(const ull*)(hrow + 4);
                ull h3 = *(const ull*)(hrow + 6);
                ulonglong2 wa = *(const ulonglong2*)&Wsd[j * 128 + cg];
                ulonglong2 wb = *(const ulonglong2*)&Wsd[j * 128 + cg + 2];
                acc[0][0] = ffma2(h0, wa.x, acc[0][0]);
                acc[0][1] = ffma2(h0, wa.y, acc[0][1]);
                acc[0][2] = ffma2(h0, wb.x, acc[0][2]);
                acc[0][3] = ffma2(h0, wb.y, acc[0][3]);
                acc[1][0] = ffma2(h1, wa.x, acc[1][0]);
                acc[1][1] = ffma2(h1, wa.y, acc[1][1]);
                acc[1][2] = ffma2(h1, wb.x, acc[1][2]);
                acc[1][3] = ffma2(h1, wb.y, acc[1][3]);
                acc[2][0] = ffma2(h2, wa.x, acc[2][0]);
                acc[2][1] = ffma2(h2, wa.y, acc[2][1]);
                acc[2][2] = ffma2(h2, wb.x, acc[2][2]);
                acc[2][3] = ffma2(h2, wb.y, acc[2][3]);
                acc[3][0] = ffma2(h3, wa.x, acc[3][0]);
                acc[3][1] = ffma2(h3, wa.y, acc[3][1]);
                acc[3][2] = ffma2(h3, wb.x, acc[3][2]);
                acc[3][3] = ffma2(h3, wb.y, acc[3][3]);
            }
        }

        float4 bb = *(const float4*)&ball[p4 * 128 + cg];
        bool do_store = (p4 < 3) || (cg < 84);
        #pragma unroll
        for (int pp = 0; pp < 4; pp++) {
            float2 c0 = unpack2(acc[pp][0]);
            float2 c1 = unpack2(acc[pp][1]);
            float2 c2 = unpack2(acc[pp][2]);
            float2 c3 = unpack2(acc[pp][3]);
            int r0 = n0 + ng * 8 + 2 * pp;
            #pragma unroll
            for (int rr = 0; rr < 2; rr++) {
                int row = r0 + rr;
                if (row < n && do_store) {
                    float vx = (rr == 0) ? c0.x : c0.y;
                    float vy = (rr == 0) ? c1.x : c1.y;
                    float vz = (rr == 0) ? c2.x : c2.y;
                    float vw = (rr == 0) ? c3.x : c3.y;
                    float4 o = make_float4(vx + bb.x, vy + bb.y, vz + bb.z, vw + bb.w);
                    float* dst;
                    if (p4 == 0)      dst = g_q  + (size_t)row * 256 + cg;
                    else if (p4 == 1) dst = g_kv + (size_t)row * 256 + cg;
                    else if (p4 == 2) dst = g_kv + (size_t)row * 256 + 128 + cg;
                    else              dst = g_q  + (size_t)row * 256 + 128 + cg;
                    *(float4*)dst = o;
                }
            }
        }
    }
}

// ---------------- CSR gather attention (2-edge unrolled, packed f32x2 shuffles) ----------------
__global__ void __launch_bounds__(256) gather_kernel(int layer, int n) {
    __shared__ float Wfs[1024];
    __shared__ float bfs[128];
    __shared__ float ss[128];
    int tid = threadIdx.x;
    {
        const float* Wf = g_Wf + layer * 1024;
        const float* bf = g_bf + layer * 128;
        for (int i = tid; i < 1024; i += 256) Wfs[i] = Wf[i];
        if (tid < 128) { bfs[tid] = bf[tid]; ss[tid] = 0.f; }
    }
    __syncthreads();

    int lane = tid & 31;
    int warp = tid >> 5;
    int head = lane >> 4;
    int jj = lane & 15;
    int l4 = jj * 4;
    bool isj = jj < 8;

    float bns0 = 0.f, bns1 = 0.f, bns2 = 0.f, bns3 = 0.f;
    float bq0 = 0.f, bq1 = 0.f, bq2 = 0.f, bq3 = 0.f;

    int nwarps = gridDim.x * (blockDim.x >> 5);
    for (int nn = blockIdx.x * (blockDim.x >> 5) + warp; nn < n; nn += nwarps) {
        const float* bq_ = g_q + (size_t)nn * 256;
        float4 q4 = *(const float4*)(bq_ + lane * 4);
        float u = isj ? bq_[192 + head * 8 + jj] : 0.f;
        float qb = bq_[208 + head];
        int off0 = g_off[nn], off1 = g_off[nn + 1];

        float4 vacc = make_float4(0.f, 0.f, 0.f, 0.f);
        float den = 0.f, t = 0.f;

        int idx = off0;
        for (; idx + 2 <= off1; idx += 2) {
            int s0 = g_srcs[idx];
            int s1 = g_srcs[idx + 1];
            float ea0 = isj ? g_eatp[(size_t)idx * 8 + jj] : 0.f;
            float ea1 = isj ? g_eatp[(size_t)idx * 8 + 8 + jj] : 0.f;
            const float* kv0 = g_kv + (size_t)s0 * 256;
            const float* kv1 = g_kv + (size_t)s1 * 256;
            float4 k0 = *(const float4*)(kv0 + lane * 4);
            float4 v0 = *(const float4*)(kv0 + 128 + lane * 4);
            float4 k1 = *(const float4*)(kv1 + lane * 4);
            float4 v1 = *(const float4*)(kv1 + 128 + lane * 4);
            float p0 = q4.x * k0.x + q4.y * k0.y + q4.z * k0.z + q4.w * k0.w + ea0 * u;
            float p1 = q4.x * k1.x + q4.y * k1.y + q4.z * k1.z + q4.w * k1.w + ea1 * u;
            // packed two-edge reduction over 16 lanes (4 shuffles instead of 8)
            ull pp = pack2(p0, p1);
            pp = add2(pp, __shfl_xor_sync(0xffffffffu, pp, 8));
            pp = add2(pp, __shfl_xor_sync(0xffffffffu, pp, 4));
            pp = add2(pp, __shfl_xor_sync(0xffffffffu, pp, 2));
            pp = add2(pp, __shfl_xor_sync(0xffffffffu, pp, 1));
            float2 pr = unpack2(pp);
            float a0 = __expf(pr.x + qb);
            float a1 = __expf(pr.y + qb);
            vacc.x += a0 * v0.x + a1 * v1.x;
            vacc.y += a0 * v0.y + a1 * v1.y;
            vacc.z += a0 * v0.z + a1 * v1.z;
            vacc.w += a0 * v0.w + a1 * v1.w;
            den += a0 + a1;
            t += a0 * ea0 + a1 * ea1;
        }
        if (idx < off1) {
            int s0 = g_srcs[idx];
            float ea0 = isj ? g_eatp[(size_t)idx * 8 + jj] : 0.f;
            const float* kv0 = g_kv + (size_t)s0 * 256;
            float4 k0 = *(const float4*)(kv0 + lane * 4);
            float4 v0 = *(const float4*)(kv0 + 128 + lane * 4);
            float p0 = q4.x * k0.x + q4.y * k0.y + q4.z * k0.z + q4.w * k0.w + ea0 * u;
            p0 += __shfl_xor_sync(0xffffffffu, p0, 8);
            p0 += __shfl_xor_sync(0xffffffffu, p0, 4);
            p0 += __shfl_xor_sync(0xffffffffu, p0, 2);
            p0 += __shfl_xor_sync(0xffffffffu, p0, 1);
            float a0 = __expf(p0 + qb);
            vacc.x += a0 * v0.x;
            vacc.y += a0 * v0.y;
            vacc.z += a0 * v0.z;
            vacc.w += a0 * v0.w;
            den += a0;
            t += a0 * ea0;
        }

        // reconstruct edge-attr contribution: (Σ a·eat) @ Wf + den·bf
        float4 ep;
        ep.x = den * bfs[head * 64 + l4 + 0];
        ep.y = den * bfs[head * 64 + l4 + 1];
        ep.z = den * bfs[head * 64 + l4 + 2];
        ep.w = den * bfs[head * 64 + l4 + 3];
        #pragma unroll
        for (int j = 0; j < 8; j++) {
            float tj = __shfl_sync(0xffffffffu, t, (head << 4) + j);
            float4 w = *(float4*)&Wfs[j * 128 + head * 64 + l4];
            ep.x += tj * w.x; ep.y += tj * w.y; ep.z += tj * w.z; ep.w += tj * w.w;
        }
        float inv = (den > 0.f) ? 0.5f / den : 0.f;
        float4 agg = make_float4((vacc.x + ep.x) * inv, (vacc.y + ep.y) * inv,
                                 (vacc.z + ep.z) * inv, (vacc.w + ep.w) * inv);
        // packed cross-head reduction (2 shuffles instead of 4)
        ull axy = pack2(agg.x, agg.y);
        ull azw = pack2(agg.z, agg.w);
        axy = add2(axy, __shfl_xor_sync(0xffffffffu, axy, 16));
        azw = add2(azw, __shfl_xor_sync(0xffffffffu, azw, 16));
        float2 rxy = unpack2(axy);
        float2 rzw = unpack2(azw);

        if (lane < 16) {
            float4 skip = *(const float4*)(bq_ + 128 + l4);
            float4 o = make_float4(rxy.x + skip.x, rxy.y + skip.y,
                                   rzw.x + skip.z, rzw.y + skip.w);
            *(float4*)&g_outp[(size_t)nn * 64 + l4] = o;
            bns0 += o.x; bns1 += o.y; bns2 += o.z; bns3 += o.w;
            bq0 += o.x * o.x; bq1 += o.y * o.y; bq2 += o.z * o.z; bq3 += o.w * o.w;
        }
    }

    if (lane < 16) {
        atomicAdd(&ss[l4 + 0], bns0);
        atomicAdd(&ss[l4 + 1], bns1);
        atomicAdd(&ss[l4 + 2], bns2);
        atomicAdd(&ss[l4 + 3], bns3);
        atomicAdd(&ss[64 + l4 + 0], bq0);
        atomicAdd(&ss[64 + l4 + 1], bq1);
        atomicAdd(&ss[64 + l4 + 2], bq2);
        atomicAdd(&ss[64 + l4 + 3], bq3);
    }
    __syncthreads();
    if (tid < 128) atomicAdd(&g_stats[tid], ss[tid]);
}

// ---------------- BN params ----------------
__global__ void bnparam_kernel(float invn, int zero_pool) {
    int t = threadIdx.x;  // 64
    float s = g_stats[t], sq = g_stats[64 + t];
    float mu = s * invn;
    float var = sq * invn - mu * mu;
    g_bn[t] = mu;
    g_bn[64 + t] = rsqrtf(var + 1e-5f);
    g_stats[t] = 0.f;
    g_stats[64 + t] = 0.f;
    if (zero_pool) {
        for (int i = t; i < BG * 64; i += 64) g_pool[i] = 0.f;
        if (t < BG) g_gden[t] = 0.f;
    }
}

// ---------------- pooling with fused BN-apply + leaky_relu + residual; re-zero CSR counters ----------------
__global__ void __launch_bounds__(256) pool_kernel(const int* __restrict__ batch,
                                                   const float* __restrict__ gate_W,
                                                   const float* __restrict__ gate_b,
                                                   const float* __restrict__ gamma,
                                                   const float* __restrict__ beta, int n) {
    for (int i = blockIdx.x * blockDim.x + threadIdx.x; i < n;
         i += gridDim.x * blockDim.x) {
        g_deg[i] = 0;
        g_cur[i] = 0;
    }

    int lane = threadIdx.x & 31;
    int w = (blockIdx.x * 256 + threadIdx.x) >> 5;
    int n0 = w * 64;
    if (n0 >= n) return;
    int n1 = min(n0 + 64, n);

    int c0 = lane * 2;
    float2 gw = ((const float2*)gate_W)[lane];
    float gb = gate_b[0];
    float2 ga = make_float2(__ldg(&gamma[c0]), __ldg(&gamma[c0 + 1]));
    float2 be = make_float2(__ldg(&beta[c0]), __ldg(&beta[c0 + 1]));
    float2 mu = make_float2(g_bn[c0], g_bn[c0 + 1]);
    float2 rs = make_float2(g_bn[64 + c0], g_bn[64 + c0 + 1]);

    int cur = -1;
    float ax = 0.f, ay = 0.f, ws = 0.f;
    for (int nn = n0; nn < n1; nn++) {
        float2 hv = ((const float2*)g_h)[nn * 32 + lane];
        float2 ov = ((const float2*)g_outp)[nn * 32 + lane];
        float v0 = ga.x * (ov.x - mu.x) * rs.x + be.x;
        float v1 = ga.y * (ov.y - mu.y) * rs.y + be.y;
        v0 = (v0 > 0.f) ? v0 : 0.01f * v0;
        v1 = (v1 > 0.f) ? v1 : 0.01f * v1;
        float h0 = hv.x + v0;
        float h1 = hv.y + v1;
        float p = h0 * gw.x + h1 * gw.y;
        p += __shfl_xor_sync(0xffffffffu, p, 16);
        p += __shfl_xor_sync(0xffffffffu, p, 8);
        p += __shfl_xor_sync(0xffffffffu, p, 4);
        p += __shfl_xor_sync(0xffffffffu, p, 2);
        p += __shfl_xor_sync(0xffffffffu, p, 1);
        float wt = __expf(p + gb);
        int b = batch[nn];
        if (b != cur) {
            if (cur >= 0) {
                atomicAdd(&g_pool[cur * 64 + c0], ax);
                atomicAdd(&g_pool[cur * 64 + c0 + 1], ay);
                if (lane == 0) atomicAdd(&g_gden[cur], ws);
            }
            cur = b; ax = ay = ws = 0.f;
        }
        ax += wt * h0;
        ay += wt * h1;
        ws += wt;
    }
    if (cur >= 0) {
        atomicAdd(&g_pool[cur * 64 + c0], ax);
        atomicAdd(&g_pool[cur * 64 + c0 + 1], ay);
        if (lane == 0) atomicAdd(&g_gden[cur], ws);
    }
}

// ---------------- final readout ----------------
__global__ void final_kernel(const float* __restrict__ out_W,
                             const float* __restrict__ out_b, float* __restrict__ out) {
    int lane = threadIdx.x & 31;
    int b = (blockIdx.x * blockDim.x + threadIdx.x) >> 5;
    if (b >= BG) return;
    float2 ow = ((const float2*)out_W)[lane];
    float2 p = ((const float2*)g_pool)[b * 32 + lane];
    float gd = g_gden[b];
    float inv = (gd > 0.f) ? 1.f / gd : 0.f;
    float v = (p.x * ow.x + p.y * ow.y) * inv;
    v += __shfl_xor_sync(0xffffffffu, v, 16);
    v += __shfl_xor_sync(0xffffffffu, v, 8);
    v += __shfl_xor_sync(0xffffffffu, v, 4);
    v += __shfl_xor_sync(0xffffffffu, v, 2);
    v += __shfl_xor_sync(0xffffffffu, v, 1);
    if (lane == 0) out[b] = 1.f / (1.f + __expf(-(v + out_b[0])));
}

// ---------------- launch ----------------
extern "C" void kernel_launch(void* const* d_in, const int* in_sizes, int n_in,
                              void* d_out, int out_size) {
    const float* x      = (const float*)d_in[0];
    const float* eat    = (const float*)d_in[1];
    const int*   esrc   = (const int*)d_in[2];
    const int*   edst   = (const int*)d_in[3];
    const int*   batch  = (const int*)d_in[4];
    const float* node_W = (const float*)d_in[5];
    const float* node_b = (const float*)d_in[6];
    const float* edge_W = (const float*)d_in[7];
    const float* edge_b = (const float*)d_in[8];
    const float* Wq     = (const float*)d_in[9];
    const float* bq     = (const float*)d_in[10];
    const float* Wk     = (const float*)d_in[11];
    const float* bk     = (const float*)d_in[12];
    const float* Wv     = (const float*)d_in[13];
    const float* bv     = (const float*)d_in[14];
    const float* We     = (const float*)d_in[15];
    const float* be     = (const float*)d_in[16];
    const float* Wskip  = (const float*)d_in[17];
    const float* bskip  = (const float*)d_in[18];
    const float* gamma  = (const float*)d_in[19];
    const float* beta   = (const float*)d_in[20];
    const float* gate_W = (const float*)d_in[21];
    const float* gate_b = (const float*)d_in[22];
    const float* out_W  = (const float*)d_in[23];
    const float* out_b  = (const float*)d_in[24];
    float* out = (float*)d_out;

    int n = in_sizes[0] / 16;
    int E = in_sizes[1] / 8;
    int nb = (n + 255) / 256;
    int qkvs_blocks = (n + 63) / 64;
    float invn = 1.0f / (float)n;

    // launch order keeps qkvs (layer 0) at slot #3 -> gets ncu-profiled
    setup1_kernel<<<128, 256>>>(Wq, bq, Wk, bk, Wv, bv, Wskip, bskip,
                                edge_W, edge_b, We, be);                       // 0
    setup2_kernel<<<(2 * 64 * 18 + 2 * 18 + 255) / 256, 256>>>();              // 1
    node_enc_kernel<<<(n * 64 + 255) / 256, 256>>>(x, node_W, node_b, n);      // 2
    qkvs_kernel<<<qkvs_blocks, 256>>>(0, n, 0, gamma, beta);                   // 3 (profiled)

    csr_hist_kernel<<<(E + 255) / 256, 256>>>(edst, E);                        // 4
    scan1_kernel<<<nb, 256>>>(n);                                              // 5
    scan2_kernel<<<1, 256>>>(nb, n, E);                                        // 6
    scan3_kernel<<<nb, 256>>>(n);                                              // 7
    csr_scatter_kernel<<<(E + 255) / 256, 256>>>(eat, esrc, edst, E);          // 8

    gather_kernel<<<1480, 256>>>(0, n);                                        // 9
    bnparam_kernel<<<1, 64>>>(invn, 0);                                        // 10
    qkvs_kernel<<<qkvs_blocks, 256>>>(1, n, 1, gamma, beta);                   // 11
    gather_kernel<<<1480, 256>>>(1, n);                                        // 12
    bnparam_kernel<<<1, 64>>>(invn, 1);                                        // 13

    int pool_blocks = ((n + 63) / 64 + 7) / 8;
    pool_kernel<<<pool_blocks, 256>>>(batch, gate_W, gate_b,
                                      gamma + 64, beta + 64, n);               // 14
    final_kernel<<<(BG * 64 + 63) / 64, 64>>>(out_W, out_b, out);              // 15
}

// round 7
// speedup vs baseline: 1.2751x; 1.2751x over previous
#include <cuda_runtime.h>
#include <math.h>

#define NN 50000
#define EE 512000
#define BG 64

// ---------------- scratch ----------------
__device__ float g_h[NN * 64];
__device__ float g_q[NN * 256];         // q'(scaled)[0:128) skip[128:192) u[192:208) qb[208:210)
__device__ float g_kv[NN * 256];        // k[0:128) v[128:256)
__device__ float g_outp[NN * 64];
__device__ float g_Wall[2 * 64 * 512];
__device__ float g_ball[2 * 512];
__device__ float g_Wf[2 * 1024];        // edge_W @ We[i]  [8,128]
__device__ float g_bf[2 * 128];
__device__ float g_stats[128];          // zeroed after each use (invariant across calls)
__device__ float g_bn[128];
__device__ float g_pool[BG * 64];
__device__ float g_gden[BG];
// CSR (g_deg/g_cur: zero-initialized at load; re-zeroed at end of each call in pool)
__device__ int g_deg[NN];
__device__ int g_cur[NN];
__device__ int g_off[NN + 1];
__device__ int g_bsum[256];
__device__ int g_boff[256];
__device__ int g_srcs[EE];
__device__ float g_eatp[EE * 8];        // edge_attr permuted into CSR order

typedef unsigned long long ull;

// ---------------- f32x2 helpers ----------------
__device__ __forceinline__ ull pack2(float x, float y) {
    ull d;
    asm("mov.b64 %0, {%1, %2};" : "=l"(d) : "r"(__float_as_uint(x)), "r"(__float_as_uint(y)));
    return d;
}
__device__ __forceinline__ ull ffma2(ull a, ull b, ull c) {
    ull d;
    asm("fma.rn.f32x2 %0, %1, %2, %3;" : "=l"(d) : "l"(a), "l"(b), "l"(c));
    return d;
}
__device__ __forceinline__ ull add2(ull a, ull b) {
    ull d;
    asm("add.rn.f32x2 %0, %1, %2;" : "=l"(d) : "l"(a), "l"(b));
    return d;
}
__device__ __forceinline__ float2 unpack2(ull v) {
    unsigned int lo, hi;
    asm("mov.b64 {%0, %1}, %2;" : "=r"(lo), "=r"(hi) : "l"(v));
    return make_float2(__uint_as_float(lo), __uint_as_float(hi));
}

// ---------------- setup1: base fused weights (q scaled by 1/8) ----------------
__global__ void setup1_kernel(const float* __restrict__ Wq, const float* __restrict__ bq,
                              const float* __restrict__ Wk, const float* __restrict__ bk,
                              const float* __restrict__ Wv, const float* __restrict__ bv,
                              const float* __restrict__ Wskip, const float* __restrict__ bskip,
                              const float* __restrict__ edge_W, const float* __restrict__ edge_b,
                              const float* __restrict__ We, const float* __restrict__ be) {
    const int TOT = 65536 + 1024 + 2048 + 256;
    for (int idx = blockIdx.x * blockDim.x + threadIdx.x; idx < TOT;
         idx += gridDim.x * blockDim.x) {
        if (idx < 65536) {
            int c = idx & 511, j = (idx >> 9) & 63, i = idx >> 15;
            float v = 0.f;
            if (c < 128)      v = 0.125f * Wq[(i * 64 + j) * 128 + c];
            else if (c < 256) v = Wk[(i * 64 + j) * 128 + (c - 128)];
            else if (c < 384) v = Wv[(i * 64 + j) * 128 + (c - 256)];
            else if (c < 448) v = Wskip[(i * 64 + j) * 64 + (c - 384)];
            g_Wall[idx] = v;
        } else if (idx < 66560) {
            int t = idx - 65536; int c = t & 511, i = t >> 9;
            float v = 0.f;
            if (c < 128)      v = 0.125f * bq[i * 128 + c];
            else if (c < 256) v = bk[i * 128 + (c - 128)];
            else if (c < 384) v = bv[i * 128 + (c - 256)];
            else if (c < 448) v = bskip[i * 64 + (c - 384)];
            g_ball[t] = v;
        } else if (idx < 68608) {
            int t = idx - 66560; int i = t >> 10; int r = t & 1023;
            int j = r >> 7; int c = r & 127;
            float acc = 0.f;
            #pragma unroll 8
            for (int m = 0; m < 64; m++) acc += edge_W[j * 64 + m] * We[(i * 64 + m) * 128 + c];
            g_Wf[t] = acc;
        } else {
            int t = idx - 68608; int i = t >> 7; int c = t & 127;
            float acc = be[i * 128 + c];
            #pragma unroll 8
            for (int m = 0; m < 64; m++) acc += edge_b[m] * We[(i * 64 + m) * 128 + c];
            g_bf[i * 128 + c] = acc;
        }
    }
}

// ---------------- setup2: u / qb columns ----------------
__global__ void setup2_kernel() {
    int idx = blockIdx.x * blockDim.x + threadIdx.x;
    if (idx < 2 * 64 * 18) {
        int i = idx / (64 * 18); int r = idx % (64 * 18);
        int m = r / 18; int col = r % 18;
        const float* Wf = g_Wf + i * 1024;
        const float* bf = g_bf + i * 128;
        const float* Wrow = g_Wall + i * 64 * 512 + m * 512;
        float acc = 0.f;
        if (col < 16) {
            int h = col >> 3, j = col & 7;
            #pragma unroll 8
            for (int c = 0; c < 64; c++) acc += Wrow[h * 64 + c] * Wf[j * 128 + h * 64 + c];
            g_Wall[i * 64 * 512 + m * 512 + 448 + col] = acc;
        } else {
            int h = col - 16;
            #pragma unroll 8
            for (int c = 0; c < 64; c++) acc += Wrow[h * 64 + c] * bf[h * 64 + c];
            g_Wall[i * 64 * 512 + m * 512 + 464 + h] = acc;
        }
    } else if (idx < 2 * 64 * 18 + 2 * 18) {
        int t = idx - 2 * 64 * 18; int i = t / 18; int col = t % 18;
        const float* Wf = g_Wf + i * 1024;
        const float* bf = g_bf + i * 128;
        const float* Brow = g_ball + i * 512;
        float acc = 0.f;
        if (col < 16) {
            int h = col >> 3, j = col & 7;
            #pragma unroll 8
            for (int c = 0; c < 64; c++) acc += Brow[h * 64 + c] * Wf[j * 128 + h * 64 + c];
            g_ball[i * 512 + 448 + col] = acc;
        } else {
            int h = col - 16;
            #pragma unroll 8
            for (int c = 0; c < 64; c++) acc += Brow[h * 64 + c] * bf[h * 64 + c];
            g_ball[i * 512 + 464 + h] = acc;
        }
    }
}

// ---------------- node encoder ----------------
__global__ void __launch_bounds__(256) node_enc_kernel(const float* __restrict__ x,
                                                       const float* __restrict__ W,
                                                       const float* __restrict__ b, int n) {
    __shared__ float Ws[16 * 64];
    __shared__ float bs[64];
    int tid = threadIdx.x;
    for (int i = tid; i < 1024; i += 256) Ws[i] = W[i];
    if (tid < 64) bs[tid] = b[tid];
    __syncthreads();
    int idx = blockIdx.x * 256 + tid;
    if (idx >= n * 64) return;
    int nn = idx >> 6, c = idx & 63;
    const float* xr = x + nn * 16;
    float acc = bs[c];
    #pragma unroll
    for (int j = 0; j < 16; j++) acc += xr[j] * Ws[j * 64 + c];
    g_h[idx] = acc;
}

// ---------------- CSR build ----------------
__global__ void csr_hist_kernel(const int* __restrict__ edst, int E) {
    int e = blockIdx.x * blockDim.x + threadIdx.x;
    if (e < E) atomicAdd(&g_deg[edst[e]], 1);
}
__global__ void scan1_kernel(int n) {
    __shared__ int sd[256];
    int i = blockIdx.x * 256 + threadIdx.x;
    int v = (i < n) ? g_deg[i] : 0;
    sd[threadIdx.x] = v;
    __syncthreads();
    for (int off = 128; off > 0; off >>= 1) {
        if (threadIdx.x < off) sd[threadIdx.x] += sd[threadIdx.x + off];
        __syncthreads();
    }
    if (threadIdx.x == 0) g_bsum[blockIdx.x] = sd[0];
}
__global__ void scan2_kernel(int nb, int n, int E) {
    __shared__ int sd[256];
    int tid = threadIdx.x;
    int v = (tid < nb) ? g_bsum[tid] : 0;
    sd[tid] = v;
    __syncthreads();
    for (int off = 1; off < 256; off <<= 1) {
        int t = (tid >= off) ? sd[tid - off] : 0;
        __syncthreads();
        sd[tid] += t;
        __syncthreads();
    }
    if (tid < nb) g_boff[tid] = sd[tid] - v;
    if (tid == 0) g_off[n] = E;
}
__global__ void scan3_kernel(int n) {
    __shared__ int sd[256];
    int tid = threadIdx.x;
    int i = blockIdx.x * 256 + tid;
    int v = (i < n) ? g_deg[i] : 0;
    sd[tid] = v;
    __syncthreads();
    for (int off = 1; off < 256; off <<= 1) {
        int t = (tid >= off) ? sd[tid - off] : 0;
        __syncthreads();
        sd[tid] += t;
        __syncthreads();
    }
    if (i < n) g_off[i] = g_boff[blockIdx.x] + sd[tid] - v;
}
__global__ void csr_scatter_kernel(const float* __restrict__ eat,
                                   const int* __restrict__ esrc, const int* __restrict__ edst,
                                   int E) {
    int e = blockIdx.x * blockDim.x + threadIdx.x;
    if (e >= E) return;
    int d = edst[e];
    int pos = atomicAdd(&g_cur[d], 1);
    int slot = g_off[d] + pos;
    g_srcs[slot] = esrc[e];
    float4 a0 = *(const float4*)(eat + (size_t)e * 8);
    float4 a1 = *(const float4*)(eat + (size_t)e * 8 + 4);
    *(float4*)(g_eatp + (size_t)slot * 8) = a0;
    *(float4*)(g_eatp + (size_t)slot * 8 + 4) = a1;
}

// ---------------- fused q'/k/v/skip/u/qb GEMM (f32x2, R5 version) ----------------
__global__ void __launch_bounds__(256, 4) qkvs_kernel(int layer, int n, int fuse,
                                                      const float* __restrict__ gamma,
                                                      const float* __restrict__ beta) {
    __shared__ float hs_t[64 * 66];
    __shared__ float Ws[32 * 128];
    const float* Wall = g_Wall + layer * 64 * 512;
    const float* ball = g_ball + layer * 512;
    int tid = threadIdx.x;
    int n0 = blockIdx.x * 64;

    for (int i = tid; i < 4096; i += 256) {
        int r = i >> 6, j = i & 63;
        int nn = n0 + r;
        float v = 0.f;
        if (nn < n) {
            if (fuse) {
                float o = g_outp[nn * 64 + j];
                float hv = g_h[nn * 64 + j];
                float bnv = __ldg(&gamma[j]) * (o - g_bn[j]) * g_bn[64 + j] + __ldg(&beta[j]);
                bnv = (bnv > 0.f) ? bnv : 0.01f * bnv;
                v = hv + bnv;
                g_h[nn * 64 + j] = v;
            } else {
                v = g_h[nn * 64 + j];
            }
        }
        hs_t[j * 66 + r] = v;
    }

    int ng = tid >> 5;
    int cg = (tid & 31) * 4;

    for (int p4 = 0; p4 < 4; p4++) {
        ull acc[4][4];
        #pragma unroll
        for (int a = 0; a < 4; a++)
            #pragma unroll
            for (int b = 0; b < 4; b++) acc[a][b] = 0ull;

        for (int half = 0; half < 2; half++) {
            __syncthreads();
            for (int i = tid; i < 4096; i += 256)
                Ws[i] = Wall[(half * 32 + (i >> 7)) * 512 + p4 * 128 + (i & 127)];
            __syncthreads();

            const float* hbase = &hs_t[half * 32 * 66 + ng * 8];
            #pragma unroll 4
            for (int j = 0; j < 32; j++) {
                const float* hrow = hbase + j * 66;
                ull h0 = *(const ull*)(hrow + 0);
                ull h1 = *(const ull*)(hrow + 2);
                ull h2 = *(const ull*)(hrow + 4);
                ull h3 = *(const ull*)(hrow + 6);
                float4 w = *(float4*)&Ws[j * 128 + cg];
                ull w0 = pack2(w.x, w.x);
                ull w1 = pack2(w.y, w.y);
                ull w2 = pack2(w.z, w.z);
                ull w3 = pack2(w.w, w.w);
                acc[0][0] = ffma2(h0, w0, acc[0][0]);
                acc[0][1] = ffma2(h0, w1, acc[0][1]);
                acc[0][2] = ffma2(h0, w2, acc[0][2]);
                acc[0][3] = ffma2(h0, w3, acc[0][3]);
                acc[1][0] = ffma2(h1, w0, acc[1][0]);
                acc[1][1] = ffma2(h1, w1, acc[1][1]);
                acc[1][2] = ffma2(h1, w2, acc[1][2]);
                acc[1][3] = ffma2(h1, w3, acc[1][3]);
                acc[2][0] = ffma2(h2, w0, acc[2][0]);
                acc[2][1] = ffma2(h2, w1, acc[2][1]);
                acc[2][2] = ffma2(h2, w2, acc[2][2]);
                acc[2][3] = ffma2(h2, w3, acc[2][3]);
                acc[3][0] = ffma2(h3, w0, acc[3][0]);
                acc[3][1] = ffma2(h3, w1, acc[3][1]);
                acc[3][2] = ffma2(h3, w2, acc[3][2]);
                acc[3][3] = ffma2(h3, w3, acc[3][3]);
            }
        }

        float4 bb = *(const float4*)&ball[p4 * 128 + cg];
        bool do_store = (p4 < 3) || (cg < 84);
        #pragma unroll
        for (int pp = 0; pp < 4; pp++) {
            float2 c0 = unpack2(acc[pp][0]);
            float2 c1 = unpack2(acc[pp][1]);
            float2 c2 = unpack2(acc[pp][2]);
            float2 c3 = unpack2(acc[pp][3]);
            int r0 = n0 + ng * 8 + 2 * pp;
            #pragma unroll
            for (int rr = 0; rr < 2; rr++) {
                int row = r0 + rr;
                if (row < n && do_store) {
                    float vx = (rr == 0) ? c0.x : c0.y;
                    float vy = (rr == 0) ? c1.x : c1.y;
                    float vz = (rr == 0) ? c2.x : c2.y;
                    float vw = (rr == 0) ? c3.x : c3.y;
                    float4 o = make_float4(vx + bb.x, vy + bb.y, vz + bb.z, vw + bb.w);
                    float* dst;
                    if (p4 == 0)      dst = g_q  + (size_t)row * 256 + cg;
                    else if (p4 == 1) dst = g_kv + (size_t)row * 256 + cg;
                    else if (p4 == 2) dst = g_kv + (size_t)row * 256 + 128 + cg;
                    else              dst = g_q  + (size_t)row * 256 + 128 + cg;
                    *(float4*)dst = o;
                }
            }
        }
    }
}

// ---------------- CSR gather attention (2-edge, software-pipelined src/eat prefetch) ----------------
__global__ void __launch_bounds__(256) gather_kernel(int layer, int n) {
    __shared__ float Wfs[1024];
    __shared__ float bfs[128];
    __shared__ float ss[128];
    int tid = threadIdx.x;
    {
        const float* Wf = g_Wf + layer * 1024;
        const float* bf = g_bf + layer * 128;
        for (int i = tid; i < 1024; i += 256) Wfs[i] = Wf[i];
        if (tid < 128) { bfs[tid] = bf[tid]; ss[tid] = 0.f; }
    }
    __syncthreads();

    int lane = tid & 31;
    int warp = tid >> 5;
    int head = lane >> 4;
    int jj = lane & 15;
    int l4 = jj * 4;
    bool isj = jj < 8;

    float bns0 = 0.f, bns1 = 0.f, bns2 = 0.f, bns3 = 0.f;
    float bq0 = 0.f, bq1 = 0.f, bq2 = 0.f, bq3 = 0.f;

    int nwarps = gridDim.x * (blockDim.x >> 5);
    for (int nn = blockIdx.x * (blockDim.x >> 5) + warp; nn < n; nn += nwarps) {
        const float* bq_ = g_q + (size_t)nn * 256;
        float4 q4 = *(const float4*)(bq_ + lane * 4);
        float u = isj ? bq_[192 + head * 8 + jj] : 0.f;
        float qb = bq_[208 + head];
        int off0 = g_off[nn], off1 = g_off[nn + 1];

        float4 vacc = make_float4(0.f, 0.f, 0.f, 0.f);
        float den = 0.f, t = 0.f;

        int idx = off0;
        if (idx + 2 <= off1) {
            // prime the pipeline
            int s0 = g_srcs[idx];
            int s1 = g_srcs[idx + 1];
            float ea0 = isj ? g_eatp[(size_t)idx * 8 + jj] : 0.f;
            float ea1 = isj ? g_eatp[(size_t)idx * 8 + 8 + jj] : 0.f;
            while (idx + 2 <= off1) {
                // issue kv loads for the current pair immediately (addresses ready)
                const float* kv0 = g_kv + (size_t)s0 * 256;
                const float* kv1 = g_kv + (size_t)s1 * 256;
                float4 k0 = *(const float4*)(kv0 + lane * 4);
                float4 v0 = *(const float4*)(kv0 + 128 + lane * 4);
                float4 k1 = *(const float4*)(kv1 + lane * 4);
                float4 v1 = *(const float4*)(kv1 + 128 + lane * 4);
                float cea0 = ea0, cea1 = ea1;
                // prefetch next pair's srcs/eat (clamped: re-reads current pair on last iter)
                int np = idx + 2;
                int pi = (np + 2 <= off1) ? np : idx;
                s0 = g_srcs[pi];
                s1 = g_srcs[pi + 1];
                ea0 = isj ? g_eatp[(size_t)pi * 8 + jj] : 0.f;
                ea1 = isj ? g_eatp[(size_t)pi * 8 + 8 + jj] : 0.f;
                // compute on current pair
                float p0 = q4.x * k0.x + q4.y * k0.y + q4.z * k0.z + q4.w * k0.w + cea0 * u;
                float p1 = q4.x * k1.x + q4.y * k1.y + q4.z * k1.z + q4.w * k1.w + cea1 * u;
                ull pp = pack2(p0, p1);
                pp = add2(pp, __shfl_xor_sync(0xffffffffu, pp, 8));
                pp = add2(pp, __shfl_xor_sync(0xffffffffu, pp, 4));
                pp = add2(pp, __shfl_xor_sync(0xffffffffu, pp, 2));
                pp = add2(pp, __shfl_xor_sync(0xffffffffu, pp, 1));
                float2 pr = unpack2(pp);
                float a0 = __expf(pr.x + qb);
                float a1 = __expf(pr.y + qb);
                vacc.x += a0 * v0.x + a1 * v1.x;
                vacc.y += a0 * v0.y + a1 * v1.y;
                vacc.z += a0 * v0.z + a1 * v1.z;
                vacc.w += a0 * v0.w + a1 * v1.w;
                den += a0 + a1;
                t += a0 * cea0 + a1 * cea1;
                idx = np;
            }
        }
        if (idx < off1) {
            int s0 = g_srcs[idx];
            float ea0 = isj ? g_eatp[(size_t)idx * 8 + jj] : 0.f;
            const float* kv0 = g_kv + (size_t)s0 * 256;
            float4 k0 = *(const float4*)(kv0 + lane * 4);
            float4 v0 = *(const float4*)(kv0 + 128 + lane * 4);
            float p0 = q4.x * k0.x + q4.y * k0.y + q4.z * k0.z + q4.w * k0.w + ea0 * u;
            p0 += __shfl_xor_sync(0xffffffffu, p0, 8);
            p0 += __shfl_xor_sync(0xffffffffu, p0, 4);
            p0 += __shfl_xor_sync(0xffffffffu, p0, 2);
            p0 += __shfl_xor_sync(0xffffffffu, p0, 1);
            float a0 = __expf(p0 + qb);
            vacc.x += a0 * v0.x;
            vacc.y += a0 * v0.y;
            vacc.z += a0 * v0.z;
            vacc.w += a0 * v0.w;
            den += a0;
            t += a0 * ea0;
        }

        // reconstruct edge-attr contribution: (Σ a·eat) @ Wf + den·bf
        float4 ep;
        ep.x = den * bfs[head * 64 + l4 + 0];
        ep.y = den * bfs[head * 64 + l4 + 1];
        ep.z = den * bfs[head * 64 + l4 + 2];
        ep.w = den * bfs[head * 64 + l4 + 3];
        #pragma unroll
        for (int j = 0; j < 8; j++) {
            float tj = __shfl_sync(0xffffffffu, t, (head << 4) + j);
            float4 w = *(float4*)&Wfs[j * 128 + head * 64 + l4];
            ep.x += tj * w.x; ep.y += tj * w.y; ep.z += tj * w.z; ep.w += tj * w.w;
        }
        float inv = (den > 0.f) ? 0.5f / den : 0.f;
        float4 agg = make_float4((vacc.x + ep.x) * inv, (vacc.y + ep.y) * inv,
                                 (vacc.z + ep.z) * inv, (vacc.w + ep.w) * inv);
        ull axy = pack2(agg.x, agg.y);
        ull azw = pack2(agg.z, agg.w);
        axy = add2(axy, __shfl_xor_sync(0xffffffffu, axy, 16));
        azw = add2(azw, __shfl_xor_sync(0xffffffffu, azw, 16));
        float2 rxy = unpack2(axy);
        float2 rzw = unpack2(azw);

        if (lane < 16) {
            float4 skip = *(const float4*)(bq_ + 128 + l4);
            float4 o = make_float4(rxy.x + skip.x, rxy.y + skip.y,
                                   rzw.x + skip.z, rzw.y + skip.w);
            *(float4*)&g_outp[(size_t)nn * 64 + l4] = o;
            bns0 += o.x; bns1 += o.y; bns2 += o.z; bns3 += o.w;
            bq0 += o.x * o.x; bq1 += o.y * o.y; bq2 += o.z * o.z; bq3 += o.w * o.w;
        }
    }

    if (lane < 16) {
        atomicAdd(&ss[l4 + 0], bns0);
        atomicAdd(&ss[l4 + 1], bns1);
        atomicAdd(&ss[l4 + 2], bns2);
        atomicAdd(&ss[l4 + 3], bns3);
        atomicAdd(&ss[64 + l4 + 0], bq0);
        atomicAdd(&ss[64 + l4 + 1], bq1);
        atomicAdd(&ss[64 + l4 + 2], bq2);
        atomicAdd(&ss[64 + l4 + 3], bq3);
    }
    __syncthreads();
    if (tid < 128) atomicAdd(&g_stats[tid], ss[tid]);
}

// ---------------- BN params ----------------
__global__ void bnparam_kernel(float invn, int zero_pool) {
    int t = threadIdx.x;  // 64
    float s = g_stats[t], sq = g_stats[64 + t];
    float mu = s * invn;
    float var = sq * invn - mu * mu;
    g_bn[t] = mu;
    g_bn[64 + t] = rsqrtf(var + 1e-5f);
    g_stats[t] = 0.f;
    g_stats[64 + t] = 0.f;
    if (zero_pool) {
        for (int i = t; i < BG * 64; i += 64) g_pool[i] = 0.f;
        if (t < BG) g_gden[t] = 0.f;
    }
}

// ---------------- pooling with fused BN-apply + leaky_relu + residual; re-zero CSR counters ----------------
__global__ void __launch_bounds__(256) pool_kernel(const int* __restrict__ batch,
                                                   const float* __restrict__ gate_W,
                                                   const float* __restrict__ gate_b,
                                                   const float* __restrict__ gamma,
                                                   const float* __restrict__ beta, int n) {
    for (int i = blockIdx.x * blockDim.x + threadIdx.x; i < n;
         i += gridDim.x * blockDim.x) {
        g_deg[i] = 0;
        g_cur[i] = 0;
    }

    int lane = threadIdx.x & 31;
    int w = (blockIdx.x * 256 + threadIdx.x) >> 5;
    int n0 = w * 64;
    if (n0 >= n) return;
    int n1 = min(n0 + 64, n);

    int c0 = lane * 2;
    float2 gw = ((const float2*)gate_W)[lane];
    float gb = gate_b[0];
    float2 ga = make_float2(__ldg(&gamma[c0]), __ldg(&gamma[c0 + 1]));
    float2 be = make_float2(__ldg(&beta[c0]), __ldg(&beta[c0 + 1]));
    float2 mu = make_float2(g_bn[c0], g_bn[c0 + 1]);
    float2 rs = make_float2(g_bn[64 + c0], g_bn[64 + c0 + 1]);

    int cur = -1;
    float ax = 0.f, ay = 0.f, ws = 0.f;
    for (int nn = n0; nn < n1; nn++) {
        float2 hv = ((const float2*)g_h)[nn * 32 + lane];
        float2 ov = ((const float2*)g_outp)[nn * 32 + lane];
        float v0 = ga.x * (ov.x - mu.x) * rs.x + be.x;
        float v1 = ga.y * (ov.y - mu.y) * rs.y + be.y;
        v0 = (v0 > 0.f) ? v0 : 0.01f * v0;
        v1 = (v1 > 0.f) ? v1 : 0.01f * v1;
        float h0 = hv.x + v0;
        float h1 = hv.y + v1;
        float p = h0 * gw.x + h1 * gw.y;
        p += __shfl_xor_sync(0xffffffffu, p, 16);
        p += __shfl_xor_sync(0xffffffffu, p, 8);
        p += __shfl_xor_sync(0xffffffffu, p, 4);
        p += __shfl_xor_sync(0xffffffffu, p, 2);
        p += __shfl_xor_sync(0xffffffffu, p, 1);
        float wt = __expf(p + gb);
        int b = batch[nn];
        if (b != cur) {
            if (cur >= 0) {
                atomicAdd(&g_pool[cur * 64 + c0], ax);
                atomicAdd(&g_pool[cur * 64 + c0 + 1], ay);
                if (lane == 0) atomicAdd(&g_gden[cur], ws);
            }
            cur = b; ax = ay = ws = 0.f;
        }
        ax += wt * h0;
        ay += wt * h1;
        ws += wt;
    }
    if (cur >= 0) {
        atomicAdd(&g_pool[cur * 64 + c0], ax);
        atomicAdd(&g_pool[cur * 64 + c0 + 1], ay);
        if (lane == 0) atomicAdd(&g_gden[cur], ws);
    }
}

// ---------------- final readout ----------------
__global__ void final_kernel(const float* __restrict__ out_W,
                             const float* __restrict__ out_b, float* __restrict__ out) {
    int lane = threadIdx.x & 31;
    int b = (blockIdx.x * blockDim.x + threadIdx.x) >> 5;
    if (b >= BG) return;
    float2 ow = ((const float2*)out_W)[lane];
    float2 p = ((const float2*)g_pool)[b * 32 + lane];
    float gd = g_gden[b];
    float inv = (gd > 0.f) ? 1.f / gd : 0.f;
    float v = (p.x * ow.x + p.y * ow.y) * inv;
    v += __shfl_xor_sync(0xffffffffu, v, 16);
    v += __shfl_xor_sync(0xffffffffu, v, 8);
    v += __shfl_xor_sync(0xffffffffu, v, 4);
    v += __shfl_xor_sync(0xffffffffu, v, 2);
    v += __shfl_xor_sync(0xffffffffu, v, 1);
    if (lane == 0) out[b] = 1.f / (1.f + __expf(-(v + out_b[0])));
}

// ---------------- launch ----------------
extern "C" void kernel_launch(void* const* d_in, const int* in_sizes, int n_in,
                              void* d_out, int out_size) {
    const float* x      = (const float*)d_in[0];
    const float* eat    = (const float*)d_in[1];
    const int*   esrc   = (const int*)d_in[2];
    const int*   edst   = (const int*)d_in[3];
    const int*   batch  = (const int*)d_in[4];
    const float* node_W = (const float*)d_in[5];
    const float* node_b = (const float*)d_in[6];
    const float* edge_W = (const float*)d_in[7];
    const float* edge_b = (const float*)d_in[8];
    const float* Wq     = (const float*)d_in[9];
    const float* bq     = (const float*)d_in[10];
    const float* Wk     = (const float*)d_in[11];
    const float* bk     = (const float*)d_in[12];
    const float* Wv     = (const float*)d_in[13];
    const float* bv     = (const float*)d_in[14];
    const float* We     = (const float*)d_in[15];
    const float* be     = (const float*)d_in[16];
    const float* Wskip  = (const float*)d_in[17];
    const float* bskip  = (const float*)d_in[18];
    const float* gamma  = (const float*)d_in[19];
    const float* beta   = (const float*)d_in[20];
    const float* gate_W = (const float*)d_in[21];
    const float* gate_b = (const float*)d_in[22];
    const float* out_W  = (const float*)d_in[23];
    const float* out_b  = (const float*)d_in[24];
    float* out = (float*)d_out;

    int n = in_sizes[0] / 16;
    int E = in_sizes[1] / 8;
    int nb = (n + 255) / 256;
    int qkvs_blocks = (n + 63) / 64;
    float invn = 1.0f / (float)n;

    // launch order keeps qkvs (layer 0) at slot #3 -> gets ncu-profiled
    setup1_kernel<<<128, 256>>>(Wq, bq, Wk, bk, Wv, bv, Wskip, bskip,
                                edge_W, edge_b, We, be);                       // 0
    setup2_kernel<<<(2 * 64 * 18 + 2 * 18 + 255) / 256, 256>>>();              // 1
    node_enc_kernel<<<(n * 64 + 255) / 256, 256>>>(x, node_W, node_b, n);      // 2
    qkvs_kernel<<<qkvs_blocks, 256>>>(0, n, 0, gamma, beta);                   // 3 (profiled)

    csr_hist_kernel<<<(E + 255) / 256, 256>>>(edst, E);                        // 4
    scan1_kernel<<<nb, 256>>>(n);                                              // 5
    scan2_kernel<<<1, 256>>>(nb, n, E);                                        // 6
    scan3_kernel<<<nb, 256>>>(n);                                              // 7
    csr_scatter_kernel<<<(E + 255) / 256, 256>>>(eat, esrc, edst, E);          // 8

    gather_kernel<<<1480, 256>>>(0, n);                                        // 9
    bnparam_kernel<<<1, 64>>>(invn, 0);                                        // 10
    qkvs_kernel<<<qkvs_blocks, 256>>>(1, n, 1, gamma, beta);                   // 11
    gather_kernel<<<1480, 256>>>(1, n);                                        // 12
    bnparam_kernel<<<1, 64>>>(invn, 1);                                        // 13

    int pool_blocks = ((n + 63) / 64 + 7) / 8;
    pool_kernel<<<pool_blocks, 256>>>(batch, gate_W, gate_b,
                                      gamma + 64, beta + 64, n);               // 14
    final_kernel<<<(BG * 64 + 63) / 64, 64>>>(out_W, out_b, out);              // 15
}

// round 8
// speedup vs baseline: 1.3293x; 1.0425x over previous
#include <cuda_runtime.h>
#include <math.h>

#define NN 50000
#define EE 512000
#define BG 64

// ---------------- scratch ----------------
__device__ float g_h[NN * 64];
__device__ float g_q[NN * 256];          // q'(scaled)[0:128) skip[128:192) u[192:208) qb[208:210)
__device__ unsigned int g_kvh[NN * 128]; // bf16x2: k[0:64) v[64:128)  (25.6 MB gather set)
__device__ float g_outp[NN * 64];
__device__ float g_Wall[2 * 64 * 512];
__device__ float g_ball[2 * 512];
__device__ float g_Wf[2 * 1024];
__device__ float g_bf[2 * 128];
__device__ float g_stats[128];
__device__ float g_bn[128];
__device__ float g_pool[BG * 64];
__device__ float g_gden[BG];
// CSR
__device__ int g_deg[NN];
__device__ int g_cur[NN];
__device__ int g_off[NN + 1];
__device__ int g_bsum[256];
__device__ int g_boff[256];
__device__ int g_srcs[EE];
__device__ float g_eatp[EE * 8];

typedef unsigned long long ull;

// ---------------- f32x2 / bf16 helpers ----------------
__device__ __forceinline__ ull pack2(float x, float y) {
    ull d;
    asm("mov.b64 %0, {%1, %2};" : "=l"(d) : "r"(__float_as_uint(x)), "r"(__float_as_uint(y)));
    return d;
}
__device__ __forceinline__ ull ffma2(ull a, ull b, ull c) {
    ull d;
    asm("fma.rn.f32x2 %0, %1, %2, %3;" : "=l"(d) : "l"(a), "l"(b), "l"(c));
    return d;
}
__device__ __forceinline__ ull add2(ull a, ull b) {
    ull d;
    asm("add.rn.f32x2 %0, %1, %2;" : "=l"(d) : "l"(a), "l"(b));
    return d;
}
__device__ __forceinline__ float2 unpack2(ull v) {
    unsigned int lo, hi;
    asm("mov.b64 {%0, %1}, %2;" : "=r"(lo), "=r"(hi) : "l"(v));
    return make_float2(__uint_as_float(lo), __uint_as_float(hi));
}
// pack two f32 into bf16x2 (lo = x, hi = y)
__device__ __forceinline__ unsigned int bfpack(float x, float y) {
    unsigned int d;
    asm("cvt.rn.bf16x2.f32 %0, %1, %2;" : "=r"(d) : "f"(y), "f"(x));
    return d;
}
// unpack bf16x2 -> two f32 (exact)
__device__ __forceinline__ float bflo(unsigned int w) { return __uint_as_float(w << 16); }
__device__ __forceinline__ float bfhi(unsigned int w) { return __uint_as_float(w & 0xffff0000u); }

// ---------------- setup1 ----------------
__global__ void setup1_kernel(const float* __restrict__ Wq, const float* __restrict__ bq,
                              const float* __restrict__ Wk, const float* __restrict__ bk,
                              const float* __restrict__ Wv, const float* __restrict__ bv,
                              const float* __restrict__ Wskip, const float* __restrict__ bskip,
                              const float* __restrict__ edge_W, const float* __restrict__ edge_b,
                              const float* __restrict__ We, const float* __restrict__ be) {
    const int TOT = 65536 + 1024 + 2048 + 256;
    for (int idx = blockIdx.x * blockDim.x + threadIdx.x; idx < TOT;
         idx += gridDim.x * blockDim.x) {
        if (idx < 65536) {
            int c = idx & 511, j = (idx >> 9) & 63, i = idx >> 15;
            float v = 0.f;
            if (c < 128)      v = 0.125f * Wq[(i * 64 + j) * 128 + c];
            else if (c < 256) v = Wk[(i * 64 + j) * 128 + (c - 128)];
            else if (c < 384) v = Wv[(i * 64 + j) * 128 + (c - 256)];
            else if (c < 448) v = Wskip[(i * 64 + j) * 64 + (c - 384)];
            g_Wall[idx] = v;
        } else if (idx < 66560) {
            int t = idx - 65536; int c = t & 511, i = t >> 9;
            float v = 0.f;
            if (c < 128)      v = 0.125f * bq[i * 128 + c];
            else if (c < 256) v = bk[i * 128 + (c - 128)];
            else if (c < 384) v = bv[i * 128 + (c - 256)];
            else if (c < 448) v = bskip[i * 64 + (c - 384)];
            g_ball[t] = v;
        } else if (idx < 68608) {
            int t = idx - 66560; int i = t >> 10; int r = t & 1023;
            int j = r >> 7; int c = r & 127;
            float acc = 0.f;
            #pragma unroll 8
            for (int m = 0; m < 64; m++) acc += edge_W[j * 64 + m] * We[(i * 64 + m) * 128 + c];
            g_Wf[t] = acc;
        } else {
            int t = idx - 68608; int i = t >> 7; int c = t & 127;
            float acc = be[i * 128 + c];
            #pragma unroll 8
            for (int m = 0; m < 64; m++) acc += edge_b[m] * We[(i * 64 + m) * 128 + c];
            g_bf[i * 128 + c] = acc;
        }
    }
}

// ---------------- setup2 ----------------
__global__ void setup2_kernel() {
    int idx = blockIdx.x * blockDim.x + threadIdx.x;
    if (idx < 2 * 64 * 18) {
        int i = idx / (64 * 18); int r = idx % (64 * 18);
        int m = r / 18; int col = r % 18;
        const float* Wf = g_Wf + i * 1024;
        const float* bf = g_bf + i * 128;
        const float* Wrow = g_Wall + i * 64 * 512 + m * 512;
        float acc = 0.f;
        if (col < 16) {
            int h = col >> 3, j = col & 7;
            #pragma unroll 8
            for (int c = 0; c < 64; c++) acc += Wrow[h * 64 + c] * Wf[j * 128 + h * 64 + c];
            g_Wall[i * 64 * 512 + m * 512 + 448 + col] = acc;
        } else {
            int h = col - 16;
            #pragma unroll 8
            for (int c = 0; c < 64; c++) acc += Wrow[h * 64 + c] * bf[h * 64 + c];
            g_Wall[i * 64 * 512 + m * 512 + 464 + h] = acc;
        }
    } else if (idx < 2 * 64 * 18 + 2 * 18) {
        int t = idx - 2 * 64 * 18; int i = t / 18; int col = t % 18;
        const float* Wf = g_Wf + i * 1024;
        const float* bf = g_bf + i * 128;
        const float* Brow = g_ball + i * 512;
        float acc = 0.f;
        if (col < 16) {
            int h = col >> 3, j = col & 7;
            #pragma unroll 8
            for (int c = 0; c < 64; c++) acc += Brow[h * 64 + c] * Wf[j * 128 + h * 64 + c];
            g_ball[i * 512 + 448 + col] = acc;
        } else {
            int h = col - 16;
            #pragma unroll 8
            for (int c = 0; c < 64; c++) acc += Brow[h * 64 + c] * bf[h * 64 + c];
            g_ball[i * 512 + 464 + h] = acc;
        }
    }
}

// ---------------- node encoder ----------------
__global__ void __launch_bounds__(256) node_enc_kernel(const float* __restrict__ x,
                                                       const float* __restrict__ W,
                                                       const float* __restrict__ b, int n) {
    __shared__ float Ws[16 * 64];
    __shared__ float bs[64];
    int tid = threadIdx.x;
    for (int i = tid; i < 1024; i += 256) Ws[i] = W[i];
    if (tid < 64) bs[tid] = b[tid];
    __syncthreads();
    int idx = blockIdx.x * 256 + tid;
    if (idx >= n * 64) return;
    int nn = idx >> 6, c = idx & 63;
    const float* xr = x + nn * 16;
    float acc = bs[c];
    #pragma unroll
    for (int j = 0; j < 16; j++) acc += xr[j] * Ws[j * 64 + c];
    g_h[idx] = acc;
}

// ---------------- CSR build ----------------
__global__ void csr_hist_kernel(const int* __restrict__ edst, int E) {
    int e = blockIdx.x * blockDim.x + threadIdx.x;
    if (e < E) atomicAdd(&g_deg[edst[e]], 1);
}
__global__ void scan1_kernel(int n) {
    __shared__ int sd[256];
    int i = blockIdx.x * 256 + threadIdx.x;
    int v = (i < n) ? g_deg[i] : 0;
    sd[threadIdx.x] = v;
    __syncthreads();
    for (int off = 128; off > 0; off >>= 1) {
        if (threadIdx.x < off) sd[threadIdx.x] += sd[threadIdx.x + off];
        __syncthreads();
    }
    if (threadIdx.x == 0) g_bsum[blockIdx.x] = sd[0];
}
__global__ void scan2_kernel(int nb, int n, int E) {
    __shared__ int sd[256];
    int tid = threadIdx.x;
    int v = (tid < nb) ? g_bsum[tid] : 0;
    sd[tid] = v;
    __syncthreads();
    for (int off = 1; off < 256; off <<= 1) {
        int t = (tid >= off) ? sd[tid - off] : 0;
        __syncthreads();
        sd[tid] += t;
        __syncthreads();
    }
    if (tid < nb) g_boff[tid] = sd[tid] - v;
    if (tid == 0) g_off[n] = E;
}
__global__ void scan3_kernel(int n) {
    __shared__ int sd[256];
    int tid = threadIdx.x;
    int i = blockIdx.x * 256 + tid;
    int v = (i < n) ? g_deg[i] : 0;
    sd[tid] = v;
    __syncthreads();
    for (int off = 1; off < 256; off <<= 1) {
        int t = (tid >= off) ? sd[tid - off] : 0;
        __syncthreads();
        sd[tid] += t;
        __syncthreads();
    }
    if (i < n) g_off[i] = g_boff[blockIdx.x] + sd[tid] - v;
}
__global__ void csr_scatter_kernel(const float* __restrict__ eat,
                                   const int* __restrict__ esrc, const int* __restrict__ edst,
                                   int E) {
    int e = blockIdx.x * blockDim.x + threadIdx.x;
    if (e >= E) return;
    int d = edst[e];
    int pos = atomicAdd(&g_cur[d], 1);
    int slot = g_off[d] + pos;
    g_srcs[slot] = esrc[e];
    float4 a0 = *(const float4*)(eat + (size_t)e * 8);
    float4 a1 = *(const float4*)(eat + (size_t)e * 8 + 4);
    *(float4*)(g_eatp + (size_t)slot * 8) = a0;
    *(float4*)(g_eatp + (size_t)slot * 8 + 4) = a1;
}

// ---------------- fused q'/k/v/skip/u/qb GEMM (f32x2); k/v stored bf16 ----------------
__global__ void __launch_bounds__(256, 4) qkvs_kernel(int layer, int n, int fuse,
                                                      const float* __restrict__ gamma,
                                                      const float* __restrict__ beta) {
    __shared__ float hs_t[64 * 66];
    __shared__ float Ws[32 * 128];
    const float* Wall = g_Wall + layer * 64 * 512;
    const float* ball = g_ball + layer * 512;
    int tid = threadIdx.x;
    int n0 = blockIdx.x * 64;

    for (int i = tid; i < 4096; i += 256) {
        int r = i >> 6, j = i & 63;
        int nn = n0 + r;
        float v = 0.f;
        if (nn < n) {
            if (fuse) {
                float o = g_outp[nn * 64 + j];
                float hv = g_h[nn * 64 + j];
                float bnv = __ldg(&gamma[j]) * (o - g_bn[j]) * g_bn[64 + j] + __ldg(&beta[j]);
                bnv = (bnv > 0.f) ? bnv : 0.01f * bnv;
                v = hv + bnv;
                g_h[nn * 64 + j] = v;
            } else {
                v = g_h[nn * 64 + j];
            }
        }
        hs_t[j * 66 + r] = v;
    }

    int ng = tid >> 5;
    int cg = (tid & 31) * 4;

    for (int p4 = 0; p4 < 4; p4++) {
        ull acc[4][4];
        #pragma unroll
        for (int a = 0; a < 4; a++)
            #pragma unroll
            for (int b = 0; b < 4; b++) acc[a][b] = 0ull;

        for (int half = 0; half < 2; half++) {
            __syncthreads();
            for (int i = tid; i < 4096; i += 256)
                Ws[i] = Wall[(half * 32 + (i >> 7)) * 512 + p4 * 128 + (i & 127)];
            __syncthreads();

            const float* hbase = &hs_t[half * 32 * 66 + ng * 8];
            #pragma unroll 4
            for (int j = 0; j < 32; j++) {
                const float* hrow = hbase + j * 66;
                ull h0 = *(const ull*)(hrow + 0);
                ull h1 = *(const ull*)(hrow + 2);
                ull h2 = *(const ull*)(hrow + 4);
                ull h3 = *(const ull*)(hrow + 6);
                float4 w = *(float4*)&Ws[j * 128 + cg];
                ull w0 = pack2(w.x, w.x);
                ull w1 = pack2(w.y, w.y);
                ull w2 = pack2(w.z, w.z);
                ull w3 = pack2(w.w, w.w);
                acc[0][0] = ffma2(h0, w0, acc[0][0]);
                acc[0][1] = ffma2(h0, w1, acc[0][1]);
                acc[0][2] = ffma2(h0, w2, acc[0][2]);
                acc[0][3] = ffma2(h0, w3, acc[0][3]);
                acc[1][0] = ffma2(h1, w0, acc[1][0]);
                acc[1][1] = ffma2(h1, w1, acc[1][1]);
                acc[1][2] = ffma2(h1, w2, acc[1][2]);
                acc[1][3] = ffma2(h1, w3, acc[1][3]);
                acc[2][0] = ffma2(h2, w0, acc[2][0]);
                acc[2][1] = ffma2(h2, w1, acc[2][1]);
                acc[2][2] = ffma2(h2, w2, acc[2][2]);
                acc[2][3] = ffma2(h2, w3, acc[2][3]);
                acc[3][0] = ffma2(h3, w0, acc[3][0]);
                acc[3][1] = ffma2(h3, w1, acc[3][1]);
                acc[3][2] = ffma2(h3, w2, acc[3][2]);
                acc[3][3] = ffma2(h3, w3, acc[3][3]);
            }
        }

        float4 bb = *(const float4*)&ball[p4 * 128 + cg];
        bool do_store = (p4 < 3) || (cg < 84);
        #pragma unroll
        for (int pp = 0; pp < 4; pp++) {
            float2 c0 = unpack2(acc[pp][0]);
            float2 c1 = unpack2(acc[pp][1]);
            float2 c2 = unpack2(acc[pp][2]);
            float2 c3 = unpack2(acc[pp][3]);
            int r0 = n0 + ng * 8 + 2 * pp;
            #pragma unroll
            for (int rr = 0; rr < 2; rr++) {
                int row = r0 + rr;
                if (row < n && do_store) {
                    float vx = ((rr == 0) ? c0.x : c0.y) + bb.x;
                    float vy = ((rr == 0) ? c1.x : c1.y) + bb.y;
                    float vz = ((rr == 0) ? c2.x : c2.y) + bb.z;
                    float vw = ((rr == 0) ? c3.x : c3.y) + bb.w;
                    if (p4 == 0) {
                        *(float4*)&g_q[(size_t)row * 256 + cg] = make_float4(vx, vy, vz, vw);
                    } else if (p4 == 3) {
                        *(float4*)&g_q[(size_t)row * 256 + 128 + cg] = make_float4(vx, vy, vz, vw);
                    } else {
                        // k (p4==1) or v (p4==2) -> bf16x2 pairs
                        unsigned int u0 = bfpack(vx, vy);
                        unsigned int u1 = bfpack(vz, vw);
                        int base = row * 128 + ((p4 == 2) ? 64 : 0) + (cg >> 1);
                        *(uint2*)&g_kvh[base] = make_uint2(u0, u1);
                    }
                }
            }
        }
    }
}

// ---------------- CSR gather attention (2-edge unrolled, bf16 k/v) ----------------
__global__ void __launch_bounds__(256) gather_kernel(int layer, int n) {
    __shared__ float Wfs[1024];
    __shared__ float bfs[128];
    __shared__ float ss[128];
    int tid = threadIdx.x;
    {
        const float* Wf = g_Wf + layer * 1024;
        const float* bf = g_bf + layer * 128;
        for (int i = tid; i < 1024; i += 256) Wfs[i] = Wf[i];
        if (tid < 128) { bfs[tid] = bf[tid]; ss[tid] = 0.f; }
    }
    __syncthreads();

    int lane = tid & 31;
    int warp = tid >> 5;
    int head = lane >> 4;
    int jj = lane & 15;
    int l4 = jj * 4;
    bool isj = jj < 8;

    float bns0 = 0.f, bns1 = 0.f, bns2 = 0.f, bns3 = 0.f;
    float bq0 = 0.f, bq1 = 0.f, bq2 = 0.f, bq3 = 0.f;

    int nwarps = gridDim.x * (blockDim.x >> 5);
    for (int nn = blockIdx.x * (blockDim.x >> 5) + warp; nn < n; nn += nwarps) {
        const float* bq_ = g_q + (size_t)nn * 256;
        float4 q4 = *(const float4*)(bq_ + lane * 4);
        float u = isj ? bq_[192 + head * 8 + jj] : 0.f;
        float qb = bq_[208 + head];
        int off0 = g_off[nn], off1 = g_off[nn + 1];

        float4 vacc = make_float4(0.f, 0.f, 0.f, 0.f);
        float den = 0.f, t = 0.f;

        int idx = off0;
        for (; idx + 2 <= off1; idx += 2) {
            int s0 = g_srcs[idx];
            int s1 = g_srcs[idx + 1];
            float ea0 = isj ? g_eatp[(size_t)idx * 8 + jj] : 0.f;
            float ea1 = isj ? g_eatp[(size_t)idx * 8 + 8 + jj] : 0.f;
            const unsigned int* kb0 = g_kvh + (size_t)s0 * 128;
            const unsigned int* kb1 = g_kvh + (size_t)s1 * 128;
            uint2 kw0 = ((const uint2*)kb0)[lane];
            uint2 vw0 = ((const uint2*)(kb0 + 64))[lane];
            uint2 kw1 = ((const uint2*)kb1)[lane];
            uint2 vw1 = ((const uint2*)(kb1 + 64))[lane];
            float p0 = q4.x * bflo(kw0.x) + q4.y * bfhi(kw0.x)
                     + q4.z * bflo(kw0.y) + q4.w * bfhi(kw0.y) + ea0 * u;
            float p1 = q4.x * bflo(kw1.x) + q4.y * bfhi(kw1.x)
                     + q4.z * bflo(kw1.y) + q4.w * bfhi(kw1.y) + ea1 * u;
            ull pp = pack2(p0, p1);
            pp = add2(pp, __shfl_xor_sync(0xffffffffu, pp, 8));
            pp = add2(pp, __shfl_xor_sync(0xffffffffu, pp, 4));
            pp = add2(pp, __shfl_xor_sync(0xffffffffu, pp, 2));
            pp = add2(pp, __shfl_xor_sync(0xffffffffu, pp, 1));
            float2 pr = unpack2(pp);
            float a0 = __expf(pr.x + qb);
            float a1 = __expf(pr.y + qb);
            vacc.x += a0 * bflo(vw0.x) + a1 * bflo(vw1.x);
            vacc.y += a0 * bfhi(vw0.x) + a1 * bfhi(vw1.x);
            vacc.z += a0 * bflo(vw0.y) + a1 * bflo(vw1.y);
            vacc.w += a0 * bfhi(vw0.y) + a1 * bfhi(vw1.y);
            den += a0 + a1;
            t += a0 * ea0 + a1 * ea1;
        }
        if (idx < off1) {
            int s0 = g_srcs[idx];
            float ea0 = isj ? g_eatp[(size_t)idx * 8 + jj] : 0.f;
            const unsigned int* kb0 = g_kvh + (size_t)s0 * 128;
            uint2 kw0 = ((const uint2*)kb0)[lane];
            uint2 vw0 = ((const uint2*)(kb0 + 64))[lane];
            float p0 = q4.x * bflo(kw0.x) + q4.y * bfhi(kw0.x)
                     + q4.z * bflo(kw0.y) + q4.w * bfhi(kw0.y) + ea0 * u;
            p0 += __shfl_xor_sync(0xffffffffu, p0, 8);
            p0 += __shfl_xor_sync(0xffffffffu, p0, 4);
            p0 += __shfl_xor_sync(0xffffffffu, p0, 2);
            p0 += __shfl_xor_sync(0xffffffffu, p0, 1);
            float a0 = __expf(p0 + qb);
            vacc.x += a0 * bflo(vw0.x);
            vacc.y += a0 * bfhi(vw0.x);
            vacc.z += a0 * bflo(vw0.y);
            vacc.w += a0 * bfhi(vw0.y);
            den += a0;
            t += a0 * ea0;
        }

        // reconstruct edge-attr contribution: (Σ a·eat) @ Wf + den·bf
        float4 ep;
        ep.x = den * bfs[head * 64 + l4 + 0];
        ep.y = den * bfs[head * 64 + l4 + 1];
        ep.z = den * bfs[head * 64 + l4 + 2];
        ep.w = den * bfs[head * 64 + l4 + 3];
        #pragma unroll
        for (int j = 0; j < 8; j++) {
            float tj = __shfl_sync(0xffffffffu, t, (head << 4) + j);
            float4 w = *(float4*)&Wfs[j * 128 + head * 64 + l4];
            ep.x += tj * w.x; ep.y += tj * w.y; ep.z += tj * w.z; ep.w += tj * w.w;
        }
        float inv = (den > 0.f) ? 0.5f / den : 0.f;
        float4 agg = make_float4((vacc.x + ep.x) * inv, (vacc.y + ep.y) * inv,
                                 (vacc.z + ep.z) * inv, (vacc.w + ep.w) * inv);
        ull axy = pack2(agg.x, agg.y);
        ull azw = pack2(agg.z, agg.w);
        axy = add2(axy, __shfl_xor_sync(0xffffffffu, axy, 16));
        azw = add2(azw, __shfl_xor_sync(0xffffffffu, azw, 16));
        float2 rxy = unpack2(axy);
        float2 rzw = unpack2(azw);

        if (lane < 16) {
            float4 skip = *(const float4*)(bq_ + 128 + l4);
            float4 o = make_float4(rxy.x + skip.x, rxy.y + skip.y,
                                   rzw.x + skip.z, rzw.y + skip.w);
            *(float4*)&g_outp[(size_t)nn * 64 + l4] = o;
            bns0 += o.x; bns1 += o.y; bns2 += o.z; bns3 += o.w;
            bq0 += o.x * o.x; bq1 += o.y * o.y; bq2 += o.z * o.z; bq3 += o.w * o.w;
        }
    }

    if (lane < 16) {
        atomicAdd(&ss[l4 + 0], bns0);
        atomicAdd(&ss[l4 + 1], bns1);
        atomicAdd(&ss[l4 + 2], bns2);
        atomicAdd(&ss[l4 + 3], bns3);
        atomicAdd(&ss[64 + l4 + 0], bq0);
        atomicAdd(&ss[64 + l4 + 1], bq1);
        atomicAdd(&ss[64 + l4 + 2], bq2);
        atomicAdd(&ss[64 + l4 + 3], bq3);
    }
    __syncthreads();
    if (tid < 128) atomicAdd(&g_stats[tid], ss[tid]);
}

// ---------------- BN params ----------------
__global__ void bnparam_kernel(float invn, int zero_pool) {
    int t = threadIdx.x;  // 64
    float s = g_stats[t], sq = g_stats[64 + t];
    float mu = s * invn;
    float var = sq * invn - mu * mu;
    g_bn[t] = mu;
    g_bn[64 + t] = rsqrtf(var + 1e-5f);
    g_stats[t] = 0.f;
    g_stats[64 + t] = 0.f;
    if (zero_pool) {
        for (int i = t; i < BG * 64; i += 64) g_pool[i] = 0.f;
        if (t < BG) g_gden[t] = 0.f;
    }
}

// ---------------- pooling with fused BN-apply + leaky_relu + residual ----------------
__global__ void __launch_bounds__(256) pool_kernel(const int* __restrict__ batch,
                                                   const float* __restrict__ gate_W,
                                                   const float* __restrict__ gate_b,
                                                   const float* __restrict__ gamma,
                                                   const float* __restrict__ beta, int n) {
    for (int i = blockIdx.x * blockDim.x + threadIdx.x; i < n;
         i += gridDim.x * blockDim.x) {
        g_deg[i] = 0;
        g_cur[i] = 0;
    }

    int lane = threadIdx.x & 31;
    int w = (blockIdx.x * 256 + threadIdx.x) >> 5;
    int n0 = w * 64;
    if (n0 >= n) return;
    int n1 = min(n0 + 64, n);

    int c0 = lane * 2;
    float2 gw = ((const float2*)gate_W)[lane];
    float gb = gate_b[0];
    float2 ga = make_float2(__ldg(&gamma[c0]), __ldg(&gamma[c0 + 1]));
    float2 be = make_float2(__ldg(&beta[c0]), __ldg(&beta[c0 + 1]));
    float2 mu = make_float2(g_bn[c0], g_bn[c0 + 1]);
    float2 rs = make_float2(g_bn[64 + c0], g_bn[64 + c0 + 1]);

    int cur = -1;
    float ax = 0.f, ay = 0.f, ws = 0.f;
    for (int nn = n0; nn < n1; nn++) {
        float2 hv = ((const float2*)g_h)[nn * 32 + lane];
        float2 ov = ((const float2*)g_outp)[nn * 32 + lane];
        float v0 = ga.x * (ov.x - mu.x) * rs.x + be.x;
        float v1 = ga.y * (ov.y - mu.y) * rs.y + be.y;
        v0 = (v0 > 0.f) ? v0 : 0.01f * v0;
        v1 = (v1 > 0.f) ? v1 : 0.01f * v1;
        float h0 = hv.x + v0;
        float h1 = hv.y + v1;
        float p = h0 * gw.x + h1 * gw.y;
        p += __shfl_xor_sync(0xffffffffu, p, 16);
        p += __shfl_xor_sync(0xffffffffu, p, 8);
        p += __shfl_xor_sync(0xffffffffu, p, 4);
        p += __shfl_xor_sync(0xffffffffu, p, 2);
        p += __shfl_xor_sync(0xffffffffu, p, 1);
        float wt = __expf(p + gb);
        int b = batch[nn];
        if (b != cur) {
            if (cur >= 0) {
                atomicAdd(&g_pool[cur * 64 + c0], ax);
                atomicAdd(&g_pool[cur * 64 + c0 + 1], ay);
                if (lane == 0) atomicAdd(&g_gden[cur], ws);
            }
            cur = b; ax = ay = ws = 0.f;
        }
        ax += wt * h0;
        ay += wt * h1;
        ws += wt;
    }
    if (cur >= 0) {
        atomicAdd(&g_pool[cur * 64 + c0], ax);
        atomicAdd(&g_pool[cur * 64 + c0 + 1], ay);
        if (lane == 0) atomicAdd(&g_gden[cur], ws);
    }
}

// ---------------- final readout ----------------
__global__ void final_kernel(const float* __restrict__ out_W,
                             const float* __restrict__ out_b, float* __restrict__ out) {
    int lane = threadIdx.x & 31;
    int b = (blockIdx.x * blockDim.x + threadIdx.x) >> 5;
    if (b >= BG) return;
    float2 ow = ((const float2*)out_W)[lane];
    float2 p = ((const float2*)g_pool)[b * 32 + lane];
    float gd = g_gden[b];
    float inv = (gd > 0.f) ? 1.f / gd : 0.f;
    float v = (p.x * ow.x + p.y * ow.y) * inv;
    v += __shfl_xor_sync(0xffffffffu, v, 16);
    v += __shfl_xor_sync(0xffffffffu, v, 8);
    v += __shfl_xor_sync(0xffffffffu, v, 4);
    v += __shfl_xor_sync(0xffffffffu, v, 2);
    v += __shfl_xor_sync(0xffffffffu, v, 1);
    if (lane == 0) out[b] = 1.f / (1.f + __expf(-(v + out_b[0])));
}

// ---------------- launch ----------------
extern "C" void kernel_launch(void* const* d_in, const int* in_sizes, int n_in,
                              void* d_out, int out_size) {
    const float* x      = (const float*)d_in[0];
    const float* eat    = (const float*)d_in[1];
    const int*   esrc   = (const int*)d_in[2];
    const int*   edst   = (const int*)d_in[3];
    const int*   batch  = (const int*)d_in[4];
    const float* node_W = (const float*)d_in[5];
    const float* node_b = (const float*)d_in[6];
    const float* edge_W = (const float*)d_in[7];
    const float* edge_b = (const float*)d_in[8];
    const float* Wq     = (const float*)d_in[9];
    const float* bq     = (const float*)d_in[10];
    const float* Wk     = (const float*)d_in[11];
    const float* bk     = (const float*)d_in[12];
    const float* Wv     = (const float*)d_in[13];
    const float* bv     = (const float*)d_in[14];
    const float* We     = (const float*)d_in[15];
    const float* be     = (const float*)d_in[16];
    const float* Wskip  = (const float*)d_in[17];
    const float* bskip  = (const float*)d_in[18];
    const float* gamma  = (const float*)d_in[19];
    const float* beta   = (const float*)d_in[20];
    const float* gate_W = (const float*)d_in[21];
    const float* gate_b = (const float*)d_in[22];
    const float* out_W  = (const float*)d_in[23];
    const float* out_b  = (const float*)d_in[24];
    float* out = (float*)d_out;

    int n = in_sizes[0] / 16;
    int E = in_sizes[1] / 8;
    int nb = (n + 255) / 256;
    int qkvs_blocks = (n + 63) / 64;
    float invn = 1.0f / (float)n;

    setup1_kernel<<<128, 256>>>(Wq, bq, Wk, bk, Wv, bv, Wskip, bskip,
                                edge_W, edge_b, We, be);                       // 0
    setup2_kernel<<<(2 * 64 * 18 + 2 * 18 + 255) / 256, 256>>>();              // 1
    node_enc_kernel<<<(n * 64 + 255) / 256, 256>>>(x, node_W, node_b, n);      // 2
    qkvs_kernel<<<qkvs_blocks, 256>>>(0, n, 0, gamma, beta);                   // 3 (profiled)

    csr_hist_kernel<<<(E + 255) / 256, 256>>>(edst, E);                        // 4
    scan1_kernel<<<nb, 256>>>(n);                                              // 5
    scan2_kernel<<<1, 256>>>(nb, n, E);                                        // 6
    scan3_kernel<<<nb, 256>>>(n);                                              // 7
    csr_scatter_kernel<<<(E + 255) / 256, 256>>>(eat, esrc, edst, E);          // 8

    gather_kernel<<<1480, 256>>>(0, n);                                        // 9
    bnparam_kernel<<<1, 64>>>(invn, 0);                                        // 10
    qkvs_kernel<<<qkvs_blocks, 256>>>(1, n, 1, gamma, beta);                   // 11
    gather_kernel<<<1480, 256>>>(1, n);                                        // 12
    bnparam_kernel<<<1, 64>>>(invn, 1);                                        // 13

    int pool_blocks = ((n + 63) / 64 + 7) / 8;
    pool_kernel<<<pool_blocks, 256>>>(batch, gate_W, gate_b,
                                      gamma + 64, beta + 64, n);               // 14
    final_kernel<<<(BG * 64 + 63) / 64, 64>>>(out_W, out_b, out);              // 15
}